// round 4
// baseline (speedup 1.0000x reference)
#include <cuda_runtime.h>
#include <cstdint>

#define BATCH  32768
#define NCODES 8192
#define DIM    256
#define BM     64
#define BN     256                 // codes per outer tile
#define NCT    (NCODES / BN)       // 32
#define DC     16                  // dims per chunk
#define NKC    (DIM / DC)          // 16
#define CAP    32
#define MARGIN 1e-4f

// ---------------- device scratch ----------------
__device__ float  g_z2[BATCH];
__device__ float  g_e2[NCODES];
__device__ int    g_idx[BATCH];
__device__ double g_part[BATCH];
__device__ int    g_candIdx[BATCH * CAP];
__device__ int    g_candCnt[BATCH];

// ---------------- smem layout ----------------
#define ATILE   528                         // 512B fragment tile + 16B pad
#define SMA_SZ  (4 * 32 * ATILE)            // 67584: 4 mtiles x 32 ktiles
#define BPAIR   528                         // paired ntile block (512B) + pad
#define BBUF_SZ (16 * 2 * BPAIR)            // 16896: 16 pairs x 2 ktiles
#define SMB0    SMA_SZ
#define SMB1    (SMB0 + BBUF_SZ)
#define SMQB    (SMB1 + BBUF_SZ)            // qbuf[64][4] floats
#define SM_TOT  (SMQB + 64 * 4 * 4)         // 102400

__device__ __forceinline__ float to_tf32(float x) {
    uint32_t r; asm("cvt.rna.tf32.f32 %0, %1;" : "=r"(r) : "f"(x));
    return __uint_as_float(r);
}
__device__ __forceinline__ void mma_tf32(float* d, const uint4& a, uint32_t b0, uint32_t b1) {
    asm volatile(
        "mma.sync.aligned.m16n8k8.row.col.f32.tf32.tf32.f32 "
        "{%0,%1,%2,%3}, {%4,%5,%6,%7}, {%8,%9}, {%0,%1,%2,%3};"
        : "+f"(d[0]), "+f"(d[1]), "+f"(d[2]), "+f"(d[3])
        : "r"(a.x), "r"(a.y), "r"(a.z), "r"(a.w), "r"(b0), "r"(b1));
}

// ---------------- row sum-of-squares (bit-matches reference grid) ----------
__global__ void rowsq_z_kernel(const float* __restrict__ x) {
    int warp = (blockIdx.x * blockDim.x + threadIdx.x) >> 5;
    int lane = threadIdx.x & 31;
    if (warp >= BATCH) return;
    const float* r = x + (size_t)warp * DIM;
    float acc = 0.f;
#pragma unroll
    for (int j = 0; j < DIM; j += 32) { float v = r[j + lane]; acc = fmaf(v, v, acc); }
#pragma unroll
    for (int off = 16; off; off >>= 1) acc += __shfl_down_sync(0xffffffffu, acc, off);
    if (lane == 0) { g_z2[warp] = acc; g_candCnt[warp] = 0; }
}
__global__ void rowsq_e_kernel(const float* __restrict__ x) {
    int warp = (blockIdx.x * blockDim.x + threadIdx.x) >> 5;
    int lane = threadIdx.x & 31;
    if (warp >= NCODES) return;
    const float* r = x + (size_t)warp * DIM;
    float acc = 0.f;
#pragma unroll
    for (int j = 0; j < DIM; j += 32) { float v = r[j + lane]; acc = fmaf(v, v, acc); }
#pragma unroll
    for (int off = 16; off; off >>= 1) acc += __shfl_down_sync(0xffffffffu, acc, off);
    if (lane == 0) g_e2[warp] = acc;
}

// ---------------- staging helpers ----------------
__device__ __forceinline__ void stageB_store(char* sm, int bbuf, const float4* vb,
                                             const int* vn, const int* vc4) {
#pragma unroll
    for (int t = 0; t < 4; t++) {
        int n = vn[t], c4 = vc4[t];
        float e[4] = {to_tf32(vb[t].x), to_tf32(vb[t].y), to_tf32(vb[t].z), to_tf32(vb[t].w)};
        int kt = c4 >> 1, slot = c4 & 1;
        int base = bbuf + ((n >> 4) * 2 + kt) * BPAIR + ((n >> 3) & 1) * 8 + slot * 4;
#pragma unroll
        for (int j = 0; j < 4; j++)
            *(float*)(sm + base + (((n & 7) << 2) | j) * 16) = e[j];
    }
}

// ---------------- tf32 mma distance kernel + candidate capture ----------------
__global__ __launch_bounds__(256, 2)
void dist_mma_kernel(const float* __restrict__ Z, const float* __restrict__ C) {
    extern __shared__ char sm[];
    const int tid  = threadIdx.x;
    const int wid  = tid >> 5;
    const int lane = tid & 31;
    const int g    = lane >> 2;
    const int tq   = lane & 3;
    const int wr   = wid >> 2;          // 0..1 : 32-row slab
    const int wc   = wid & 3;           // 0..3 : 64-code slab
    const int rowBase = blockIdx.x * BM;
    float* qbuf = (float*)(sm + SMQB);  // [64][4]

    // ---- stage A (64 x 256), tf32, fragment-permuted ----
#pragma unroll
    for (int l = 0; l < 16; l++) {
        int i4 = tid + l * 256;              // 4096 float4
        int r  = i4 >> 6;
        int c4 = i4 & 63;
        float4 v = *(const float4*)(Z + (size_t)(rowBase + r) * DIM + c4 * 4);
        float e[4] = {to_tf32(v.x), to_tf32(v.y), to_tf32(v.z), to_tf32(v.w)};
        int base = ((r >> 4) * 32 + (c4 >> 1)) * ATILE + ((c4 & 1) * 2 + ((r >> 3) & 1)) * 4;
#pragma unroll
        for (int j = 0; j < 4; j++)
            *(float*)(sm + base + (((r & 7) << 2) | j) * 16) = e[j];
    }

    // ---- prologue: B chunk (ct=0, kc=0) ----
    float4 vb[4]; int vn[4], vc4[4];
#pragma unroll
    for (int t = 0; t < 4; t++) {
        int i4 = tid + t * 256;              // 1024 float4 = 256 codes x 16 dims
        vn[t] = i4 >> 2; vc4[t] = i4 & 3;
        vb[t] = *(const float4*)(C + (size_t)vn[t] * DIM + vc4[t] * 4);
    }
    stageB_store(sm, SMB0, vb, vn, vc4);
    __syncthreads();

    float wmRun[2][2] = {{__int_as_float(0x7f800000), __int_as_float(0x7f800000)},
                         {__int_as_float(0x7f800000), __int_as_float(0x7f800000)}};
    int cur = 0;

    for (int ct = 0; ct < NCT; ct++) {
        float acc[2][4][8];
#pragma unroll
        for (int a = 0; a < 2; a++)
#pragma unroll
            for (int b = 0; b < 4; b++)
#pragma unroll
                for (int e = 0; e < 8; e++) acc[a][b][e] = 0.f;

        for (int kc = 0; kc < NKC; kc++) {
            const bool hn = !(ct == NCT - 1 && kc == NKC - 1);
            if (hn) {
                int nct = (kc == NKC - 1) ? ct + 1 : ct;
                int nkc = (kc + 1) & (NKC - 1);
                const float* src = C + (size_t)nct * BN * DIM + nkc * DC;
#pragma unroll
                for (int t = 0; t < 4; t++) {
                    int i4 = tid + t * 256;
                    vn[t] = i4 >> 2; vc4[t] = i4 & 3;
                    vb[t] = *(const float4*)(src + (size_t)vn[t] * DIM + vc4[t] * 4);
                }
            }
            const int bbase = cur ? SMB1 : SMB0;
#pragma unroll
            for (int ks = 0; ks < 2; ks++) {
                int ktg = kc * 2 + ks;
                uint4 afr[2];
#pragma unroll
                for (int mt = 0; mt < 2; mt++)
                    afr[mt] = *(const uint4*)(sm + ((wr * 2 + mt) * 32 + ktg) * ATILE + lane * 16);
#pragma unroll
                for (int pp = 0; pp < 4; pp++) {
                    uint4 bfr = *(const uint4*)(sm + bbase + ((wc * 4 + pp) * 2 + ks) * BPAIR + lane * 16);
#pragma unroll
                    for (int mt = 0; mt < 2; mt++) {
                        mma_tf32(&acc[mt][pp][0], afr[mt], bfr.x, bfr.y);
                        mma_tf32(&acc[mt][pp][4], afr[mt], bfr.z, bfr.w);
                    }
                }
            }
            if (hn) stageB_store(sm, cur ? SMB0 : SMB1, vb, vn, vc4);
            __syncthreads();
            cur ^= 1;
        }

        // ---- epilogue: dist = e2 - 2*ze, rowmin, candidate append ----
        const int ctbase = ct * BN;
        float e2v[4][2][2];
#pragma unroll
        for (int pp = 0; pp < 4; pp++)
#pragma unroll
            for (int sub = 0; sub < 2; sub++) {
                int c = ctbase + wc * 64 + pp * 16 + sub * 8 + 2 * tq;
                e2v[pp][sub][0] = __ldg(&g_e2[c]);
                e2v[pp][sub][1] = __ldg(&g_e2[c + 1]);
            }
#pragma unroll
        for (int mt = 0; mt < 2; mt++)
#pragma unroll
            for (int h = 0; h < 2; h++) {
                float m = __int_as_float(0x7f800000);
#pragma unroll
                for (int pp = 0; pp < 4; pp++)
#pragma unroll
                    for (int sub = 0; sub < 2; sub++)
#pragma unroll
                        for (int c01 = 0; c01 < 2; c01++) {
                            int ai = sub * 4 + h * 2 + c01;
                            float d = fmaf(-2.f, acc[mt][pp][ai], e2v[pp][sub][c01]);
                            acc[mt][pp][ai] = d;
                            m = fminf(m, d);
                        }
                m = fminf(m, __shfl_xor_sync(0xffffffffu, m, 1));
                m = fminf(m, __shfl_xor_sync(0xffffffffu, m, 2));
                wmRun[mt][h] = fminf(wmRun[mt][h], m);
                if (tq == 0)
                    qbuf[(wr * 32 + mt * 16 + g + h * 8) * 4 + wc] = wmRun[mt][h];
            }
        __syncthreads();
#pragma unroll
        for (int mt = 0; mt < 2; mt++)
#pragma unroll
            for (int h = 0; h < 2; h++) {
                int r = wr * 32 + mt * 16 + g + h * 8;
                float th = fminf(fminf(qbuf[r * 4 + 0], qbuf[r * 4 + 1]),
                                 fminf(qbuf[r * 4 + 2], qbuf[r * 4 + 3])) + MARGIN;
                int grow = rowBase + r;
#pragma unroll
                for (int pp = 0; pp < 4; pp++)
#pragma unroll
                    for (int sub = 0; sub < 2; sub++)
#pragma unroll
                        for (int c01 = 0; c01 < 2; c01++) {
                            float d = acc[mt][pp][sub * 4 + h * 2 + c01];
                            if (d < th) {
                                int code = ctbase + wc * 64 + pp * 16 + sub * 8 + 2 * tq + c01;
                                int pos = atomicAdd(&g_candCnt[grow], 1);
                                if (pos < CAP) g_candIdx[grow * CAP + pos] = code;
                            }
                        }
            }
        // next ct's qbuf writes are separated by NKC barriers; no extra sync
    }
}

// ---------------- exact refine (bit-exact fp32 chain, first-index ties) ------
__device__ __forceinline__ float exact_dist(const float4* zr, int code,
                                            const float* __restrict__ C, float z2) {
    const float4* cr = (const float4*)(C + (size_t)code * DIM);
    float acc = 0.f;
#pragma unroll
    for (int d4 = 0; d4 < 64; d4++) {
        float4 a = zr[d4], b = cr[d4];
        acc = fmaf(a.x, b.x, acc); acc = fmaf(a.y, b.y, acc);
        acc = fmaf(a.z, b.z, acc); acc = fmaf(a.w, b.w, acc);
    }
    float t = z2 + g_e2[code];
    return fmaf(-2.f, acc, t);
}

__global__ void refine_kernel(const float* __restrict__ Z, const float* __restrict__ C) {
    int gw = (blockIdx.x * blockDim.x + threadIdx.x) >> 5;
    int lane = threadIdx.x & 31;
    if (gw >= BATCH) return;
    int cnt = g_candCnt[gw];
    const float4* zr = (const float4*)(Z + (size_t)gw * DIM);
    float z2 = g_z2[gw];
    float bd = __int_as_float(0x7f800000);
    int bi = 0x7fffffff;
    if (cnt <= CAP) {
        for (int s = lane; s < cnt; s += 32) {
            int code = g_candIdx[gw * CAP + s];
            float dist = exact_dist(zr, code, C, z2);
            if (dist < bd || (dist == bd && code < bi)) { bd = dist; bi = code; }
        }
    } else {
        for (int code = lane; code < NCODES; code += 32) {
            float dist = exact_dist(zr, code, C, z2);
            if (dist < bd) { bd = dist; bi = code; }
        }
    }
#pragma unroll
    for (int off = 16; off; off >>= 1) {
        float od = __shfl_down_sync(0xffffffffu, bd, off);
        int oi = __shfl_down_sync(0xffffffffu, bi, off);
        if (od < bd || (od == bd && oi < bi)) { bd = od; bi = oi; }
    }
    if (lane == 0) g_idx[gw] = bi;
}

// ---------------- gather + straight-through + loss partials ----------------
__global__ void gather2_kernel(const float* __restrict__ Z, const float* __restrict__ C,
                               float* __restrict__ outZ, float* __restrict__ outIdx) {
    int gw = (blockIdx.x * blockDim.x + threadIdx.x) >> 5;
    int lane = threadIdx.x & 31;
    if (gw >= BATCH) return;
    int idx = g_idx[gw];
    const float4* zr = (const float4*)(Z + (size_t)gw * DIM);
    const float4* er = (const float4*)(C + (size_t)idx * DIM);
    float4* orow = (float4*)(outZ + (size_t)gw * DIM);
    double s = 0.0;
#pragma unroll
    for (int h = 0; h < 2; h++) {
        int i = h * 32 + lane;
        float4 z = zr[i], e = er[i];
        float dx = e.x - z.x, dy = e.y - z.y, dz = e.z - z.z, dw = e.w - z.w;
        float4 o;
        o.x = z.x + dx; o.y = z.y + dy; o.z = z.z + dz; o.w = z.w + dw;
        orow[i] = o;
        s += (double)(dx * dx) + (double)(dy * dy) + (double)(dz * dz) + (double)(dw * dw);
    }
#pragma unroll
    for (int off = 16; off; off >>= 1) s += __shfl_down_sync(0xffffffffu, s, off);
    if (lane == 0) { g_part[gw] = s; outIdx[gw] = (float)idx; }
}

__global__ void finalize_kernel(float* __restrict__ outS) {
    __shared__ double red[256];
    int t = threadIdx.x;
    double s = 0.0;
    for (int i = t; i < BATCH; i += 256) s += g_part[i];
    red[t] = s;
    __syncthreads();
#pragma unroll
    for (int off = 128; off; off >>= 1) {
        if (t < off) red[t] += red[t + off];
        __syncthreads();
    }
    if (t == 0) {
        float cb = (float)(red[0] / (double)((size_t)BATCH * DIM));
        float commit = cb;
        float vq = cb + 0.25f * commit;
        outS[0] = vq; outS[1] = cb; outS[2] = commit;
    }
}

// ---------------------------------------------------------------------------
extern "C" void kernel_launch(void* const* d_in, const int* in_sizes, int n_in,
                              void* d_out, int out_size) {
    (void)in_sizes; (void)n_in; (void)out_size;
    const float* Z = (const float*)d_in[0];
    const float* C = (const float*)d_in[1];
    float* out    = (float*)d_out;
    float* outZ   = out;
    float* outIdx = out + (size_t)BATCH * DIM;
    float* outS   = outIdx + BATCH;

    static bool attrSet = false;
    if (!attrSet) {
        cudaFuncSetAttribute(dist_mma_kernel,
                             cudaFuncAttributeMaxDynamicSharedMemorySize, SM_TOT);
        attrSet = true;
    }

    rowsq_z_kernel<<<(BATCH * 32) / 256, 256>>>(Z);
    rowsq_e_kernel<<<(NCODES * 32) / 256, 256>>>(C);
    dist_mma_kernel<<<BATCH / BM, 256, SM_TOT>>>(Z, C);
    refine_kernel<<<BATCH / 8, 256>>>(Z, C);
    gather2_kernel<<<BATCH / 8, 256>>>(Z, C, outZ, outIdx);
    finalize_kernel<<<1, 256>>>(outS);
}

// round 5
// speedup vs baseline: 1.3198x; 1.3198x over previous
#include <cuda_runtime.h>
#include <cstdint>

#define BATCH  32768
#define NCODES 8192
#define DIM    256
#define BM     128
#define BN     256
#define NCT    (NCODES / BN)        // 32 code tiles
#define DC     32                   // dims per cp.async chunk
#define NKC    (DIM / DC)           // 8 chunks per code tile
#define NCHUNK (NCT * NKC)          // 256
#define CAP    32
#define MARGIN 2e-4f

// ---------------- device scratch ----------------
__device__ float  g_z2[BATCH];
__device__ float  g_e2[NCODES];
__device__ int    g_idx[BATCH];
__device__ double g_part[BATCH];
__device__ int    g_candIdx[BATCH * CAP];
__device__ int    g_candCnt[BATCH];

// ---------------- smem layout ----------------
#define ATILE   512                          // one m16xk8 fragment tile
#define SMA_SZ  (8 * 32 * ATILE)             // 131072 : 8 mtiles x 32 ktiles
#define BROW    144                          // 36 floats (pad) -> conflict-free LDS.32
#define BCHUNK  (256 * BROW)                 // 36864
#define SMB0    SMA_SZ
#define SMB1    (SMB0 + BCHUNK)
#define SMQB    (SMB1 + BCHUNK)              // qbuf[128][4] floats
#define SM_TOT  (SMQB + 128 * 4 * 4)         // 206848

__device__ __forceinline__ uint32_t smem_u32(const void* p) {
    uint32_t a;
    asm("{ .reg .u64 t; cvta.to.shared.u64 t, %1; cvt.u32.u64 %0, t; }" : "=r"(a) : "l"(p));
    return a;
}
__device__ __forceinline__ float to_tf32(float x) {
    uint32_t r; asm("cvt.rna.tf32.f32 %0, %1;" : "=r"(r) : "f"(x));
    return __uint_as_float(r);
}
__device__ __forceinline__ void cp16(uint32_t dst, const void* src) {
    asm volatile("cp.async.cg.shared.global [%0], [%1], 16;" :: "r"(dst), "l"(src));
}
__device__ __forceinline__ void mma_tf32(float* d, const uint4& a, uint32_t b0, uint32_t b1) {
    asm volatile(
        "mma.sync.aligned.m16n8k8.row.col.f32.tf32.tf32.f32 "
        "{%0,%1,%2,%3}, {%4,%5,%6,%7}, {%8,%9}, {%0,%1,%2,%3};"
        : "+f"(d[0]), "+f"(d[1]), "+f"(d[2]), "+f"(d[3])
        : "r"(a.x), "r"(a.y), "r"(a.z), "r"(a.w), "r"(b0), "r"(b1));
}

// ---------------- row sum-of-squares (bit-matches reference grid) ----------
__global__ void rowsq_z_kernel(const float* __restrict__ x) {
    int warp = (blockIdx.x * blockDim.x + threadIdx.x) >> 5;
    int lane = threadIdx.x & 31;
    if (warp >= BATCH) return;
    const float* r = x + (size_t)warp * DIM;
    float acc = 0.f;
#pragma unroll
    for (int j = 0; j < DIM; j += 32) { float v = r[j + lane]; acc = fmaf(v, v, acc); }
#pragma unroll
    for (int off = 16; off; off >>= 1) acc += __shfl_down_sync(0xffffffffu, acc, off);
    if (lane == 0) { g_z2[warp] = acc; g_candCnt[warp] = 0; }
}
__global__ void rowsq_e_kernel(const float* __restrict__ x) {
    int warp = (blockIdx.x * blockDim.x + threadIdx.x) >> 5;
    int lane = threadIdx.x & 31;
    if (warp >= NCODES) return;
    const float* r = x + (size_t)warp * DIM;
    float acc = 0.f;
#pragma unroll
    for (int j = 0; j < DIM; j += 32) { float v = r[j + lane]; acc = fmaf(v, v, acc); }
#pragma unroll
    for (int off = 16; off; off >>= 1) acc += __shfl_down_sync(0xffffffffu, acc, off);
    if (lane == 0) g_e2[warp] = acc;
}

// ---------------- B chunk issue: 256 codes x 32 dims via cp.async ----------
__device__ __forceinline__ void issueB(const float* __restrict__ C, uint32_t sb,
                                       int chunk, int tid) {
    int ct = chunk >> 3, kc = chunk & 7;
    uint32_t bbuf = sb + ((chunk & 1) ? SMB1 : SMB0);
    const float* src0 = C + (size_t)ct * BN * DIM + kc * DC;
#pragma unroll
    for (int t = 0; t < 8; t++) {
        int q = tid + t * 256;          // 2048 16B chunks
        int n = q >> 3, j = q & 7;
        cp16(bbuf + n * BROW + j * 16, src0 + (size_t)n * DIM + j * 4);
    }
    asm volatile("cp.async.commit_group;" ::: "memory");
}

// ---------------- tf32 mma distance kernel + candidate capture --------------
__global__ __launch_bounds__(256, 1)
void dist_mma_kernel(const float* __restrict__ Z, const float* __restrict__ C) {
    extern __shared__ char sm[];
    const uint32_t sb = smem_u32(sm);
    const int tid  = threadIdx.x;
    const int wid  = tid >> 5;
    const int lane = tid & 31;
    const int g    = lane >> 2;
    const int tq   = lane & 3;
    const int wr   = wid >> 2;           // 0..1 : 64-row slab
    const int wc   = wid & 3;            // 0..3 : 64-code slab
    const int rowBase = blockIdx.x * BM;
    float* qbuf = (float*)(sm + SMQB);   // [128][4]

    // ---- stage A (128 x 256), tf32 rna, fragment-permuted ----
#pragma unroll
    for (int l = 0; l < 32; l++) {
        int i4 = tid + l * 256;          // 8192 float4
        int r  = i4 >> 6;
        int c4 = i4 & 63;
        float4 v = *(const float4*)(Z + (size_t)(rowBase + r) * DIM + c4 * 4);
        float e[4] = {to_tf32(v.x), to_tf32(v.y), to_tf32(v.z), to_tf32(v.w)};
        int base = ((r >> 4) * 32 + (c4 >> 1)) * ATILE + ((c4 & 1) * 2 + ((r >> 3) & 1)) * 4;
#pragma unroll
        for (int j = 0; j < 4; j++)
            *(float*)(sm + base + (((r & 7) << 2) | j) * 16) = e[j];
    }

    issueB(C, sb, 0, tid);   // prologue

    float wmRun[4][2];
#pragma unroll
    for (int a = 0; a < 4; a++) { wmRun[a][0] = wmRun[a][1] = __int_as_float(0x7f800000); }

    for (int ct = 0; ct < NCT; ct++) {
        float acc[4][8][4];
#pragma unroll
        for (int a = 0; a < 4; a++)
#pragma unroll
            for (int b = 0; b < 8; b++)
#pragma unroll
                for (int e = 0; e < 4; e++) acc[a][b][e] = 0.f;

        for (int kc = 0; kc < NKC; kc++) {
            const int chunk = ct * NKC + kc;
            asm volatile("cp.async.wait_group 0;" ::: "memory");
            __syncthreads();
            if (chunk + 1 < NCHUNK) issueB(C, sb, chunk + 1, tid);

            const uint32_t bb = (uint32_t)((chunk & 1) ? SMB1 : SMB0);
#pragma unroll
            for (int ks = 0; ks < 4; ks++) {
                const int ktg = kc * 4 + ks;
                uint4 afr[4];
#pragma unroll
                for (int mt = 0; mt < 4; mt++)
                    afr[mt] = *(const uint4*)(sm + ((wr * 4 + mt) * 32 + ktg) * ATILE + lane * 16);
#pragma unroll
                for (int nt = 0; nt < 8; nt++) {
                    const char* bp = sm + bb + (wc * 64 + nt * 8 + g) * BROW + (ks * 8 + tq) * 4;
                    uint32_t b0 = *(const uint32_t*)bp;
                    uint32_t b1 = *(const uint32_t*)(bp + 16);
#pragma unroll
                    for (int mt = 0; mt < 4; mt++)
                        mma_tf32(acc[mt][nt], afr[mt], b0, b1);
                }
            }
        }

        // ---- epilogue: dist = e2 - 2*ze, running rowmin, candidate append ----
        const int ctbase = ct * BN;
        float e2v[8][2];
#pragma unroll
        for (int nt = 0; nt < 8; nt++) {
            int c = ctbase + wc * 64 + nt * 8 + 2 * tq;
            e2v[nt][0] = __ldg(&g_e2[c]);
            e2v[nt][1] = __ldg(&g_e2[c + 1]);
        }
#pragma unroll
        for (int mt = 0; mt < 4; mt++)
#pragma unroll
            for (int h = 0; h < 2; h++) {
                float m = __int_as_float(0x7f800000);
#pragma unroll
                for (int nt = 0; nt < 8; nt++)
#pragma unroll
                    for (int c01 = 0; c01 < 2; c01++) {
                        int ai = h * 2 + c01;
                        float d = fmaf(-2.f, acc[mt][nt][ai], e2v[nt][c01]);
                        acc[mt][nt][ai] = d;
                        m = fminf(m, d);
                    }
                m = fminf(m, __shfl_xor_sync(0xffffffffu, m, 1));
                m = fminf(m, __shfl_xor_sync(0xffffffffu, m, 2));
                wmRun[mt][h] = fminf(wmRun[mt][h], m);
                if (tq == 0)
                    qbuf[(wr * 64 + mt * 16 + g + h * 8) * 4 + wc] = wmRun[mt][h];
            }
        __syncthreads();
#pragma unroll
        for (int mt = 0; mt < 4; mt++)
#pragma unroll
            for (int h = 0; h < 2; h++) {
                int r = wr * 64 + mt * 16 + g + h * 8;
                float th = fminf(fminf(qbuf[r * 4 + 0], qbuf[r * 4 + 1]),
                                 fminf(qbuf[r * 4 + 2], qbuf[r * 4 + 3])) + MARGIN;
                int grow = rowBase + r;
#pragma unroll
                for (int nt = 0; nt < 8; nt++)
#pragma unroll
                    for (int c01 = 0; c01 < 2; c01++) {
                        float d = acc[mt][nt][h * 2 + c01];
                        if (d < th) {
                            int code = ctbase + wc * 64 + nt * 8 + 2 * tq + c01;
                            int pos = atomicAdd(&g_candCnt[grow], 1);
                            if (pos < CAP) g_candIdx[grow * CAP + pos] = code;
                        }
                    }
            }
        // next ct's qbuf writes are separated by its first chunk barrier
    }
}

// ---------------- exact refine (bit-exact fp32 chain, first-index ties) ------
__device__ __forceinline__ float exact_dist(const float4* __restrict__ zr, int code,
                                            const float* __restrict__ C, float z2) {
    const float4* cr = (const float4*)(C + (size_t)code * DIM);
    float acc = 0.f;
#pragma unroll 4
    for (int d4 = 0; d4 < 64; d4++) {
        float4 a = zr[d4], b = cr[d4];
        acc = fmaf(a.x, b.x, acc); acc = fmaf(a.y, b.y, acc);
        acc = fmaf(a.z, b.z, acc); acc = fmaf(a.w, b.w, acc);
    }
    float t = z2 + g_e2[code];
    return fmaf(-2.f, acc, t);
}

// 8 threads per row: thread-per-candidate-slot, subgroup shfl reduce.
__global__ __launch_bounds__(256, 6)
void refine_kernel(const float* __restrict__ Z, const float* __restrict__ C) {
    int gt = blockIdx.x * blockDim.x + threadIdx.x;
    int row = gt >> 3, slot = gt & 7;
    if (row >= BATCH) return;
    int cnt = g_candCnt[row];
    const float4* zr = (const float4*)(Z + (size_t)row * DIM);
    float z2 = g_z2[row];
    float bd = __int_as_float(0x7f800000);
    int bi = 0x7fffffff;
    if (cnt <= CAP) {
        for (int s = slot; s < cnt; s += 8) {
            int code = g_candIdx[row * CAP + s];
            float dist = exact_dist(zr, code, C, z2);
            if (dist < bd || (dist == bd && code < bi)) { bd = dist; bi = code; }
        }
    } else {  // overflow fallback: exact full scan
        for (int code = slot; code < NCODES; code += 8) {
            float dist = exact_dist(zr, code, C, z2);
            if (dist < bd || (dist == bd && code < bi)) { bd = dist; bi = code; }
        }
    }
#pragma unroll
    for (int off = 4; off; off >>= 1) {
        float od = __shfl_xor_sync(0xffffffffu, bd, off);
        int oi = __shfl_xor_sync(0xffffffffu, bi, off);
        if (od < bd || (od == bd && oi < bi)) { bd = od; bi = oi; }
    }
    if (slot == 0) g_idx[row] = bi;
}

// ---------------- gather + straight-through + loss partials ----------------
__global__ void gather2_kernel(const float* __restrict__ Z, const float* __restrict__ C,
                               float* __restrict__ outZ, float* __restrict__ outIdx) {
    int gw = (blockIdx.x * blockDim.x + threadIdx.x) >> 5;
    int lane = threadIdx.x & 31;
    if (gw >= BATCH) return;
    int idx = g_idx[gw];
    const float4* zr = (const float4*)(Z + (size_t)gw * DIM);
    const float4* er = (const float4*)(C + (size_t)idx * DIM);
    float4* orow = (float4*)(outZ + (size_t)gw * DIM);
    double s = 0.0;
#pragma unroll
    for (int h = 0; h < 2; h++) {
        int i = h * 32 + lane;
        float4 z = zr[i], e = er[i];
        float dx = e.x - z.x, dy = e.y - z.y, dz = e.z - z.z, dw = e.w - z.w;
        float4 o;
        o.x = z.x + dx; o.y = z.y + dy; o.z = z.z + dz; o.w = z.w + dw;
        orow[i] = o;
        s += (double)(dx * dx) + (double)(dy * dy) + (double)(dz * dz) + (double)(dw * dw);
    }
#pragma unroll
    for (int off = 16; off; off >>= 1) s += __shfl_down_sync(0xffffffffu, s, off);
    if (lane == 0) { g_part[gw] = s; outIdx[gw] = (float)idx; }
}

__global__ void finalize_kernel(float* __restrict__ outS) {
    __shared__ double red[256];
    int t = threadIdx.x;
    double s = 0.0;
    for (int i = t; i < BATCH; i += 256) s += g_part[i];
    red[t] = s;
    __syncthreads();
#pragma unroll
    for (int off = 128; off; off >>= 1) {
        if (t < off) red[t] += red[t + off];
        __syncthreads();
    }
    if (t == 0) {
        float cb = (float)(red[0] / (double)((size_t)BATCH * DIM));
        float commit = cb;
        float vq = cb + 0.25f * commit;
        outS[0] = vq; outS[1] = cb; outS[2] = commit;
    }
}

// ---------------------------------------------------------------------------
extern "C" void kernel_launch(void* const* d_in, const int* in_sizes, int n_in,
                              void* d_out, int out_size) {
    (void)in_sizes; (void)n_in; (void)out_size;
    const float* Z = (const float*)d_in[0];
    const float* C = (const float*)d_in[1];
    float* out    = (float*)d_out;
    float* outZ   = out;
    float* outIdx = out + (size_t)BATCH * DIM;
    float* outS   = outIdx + BATCH;

    static bool attrSet = false;
    if (!attrSet) {
        cudaFuncSetAttribute(dist_mma_kernel,
                             cudaFuncAttributeMaxDynamicSharedMemorySize, SM_TOT);
        attrSet = true;
    }

    rowsq_z_kernel<<<(BATCH * 32) / 256, 256>>>(Z);
    rowsq_e_kernel<<<(NCODES * 32) / 256, 256>>>(C);
    dist_mma_kernel<<<BATCH / BM, 256, SM_TOT>>>(Z, C);
    refine_kernel<<<(BATCH * 8) / 256, 256>>>(Z, C);
    gather2_kernel<<<BATCH / 8, 256>>>(Z, C, outZ, outIdx);
    finalize_kernel<<<1, 256>>>(outS);
}